// round 1
// baseline (speedup 1.0000x reference)
#include <cuda_runtime.h>

// ---------------------------------------------------------------------------
// TorchFovea: foveated Laplacian-pyramid blend.
//   images:    (32, 3, 360, 640) f32
//   fixations: (32, 2)           f32   (x, y) pixel coords
//   output:    (32, 3, 360, 640) f32
//
// Pipeline (all fused around pointwise pyrup evaluation):
//   1. build Gaussian fovea filter f0 (719x1279) analytically, pyrdown x4
//   2. downsample chain dn1..dn5 of the images (96 planes)
//   3. recon levels 4..0:  F_i = pyrup(F_{i+1}) + (dn_i - pyrup(dn_{i+1})) * crop_i
// ---------------------------------------------------------------------------

#define NPL 96   // 32 batches * 3 channels

// level dims
#define H0 360
#define W0 640
#define H1 180
#define W1 320
#define H2 90
#define W2 160
#define H3 45
#define W3 80
#define H4 23
#define W4 40
#define H5 12
#define W5 20

// filter dims
#define F0H 719
#define F0W 1279

// ---- scratch (device globals; no allocation allowed) ----------------------
__device__ float g_f0[F0H * F0W];
__device__ float g_f1[H0 * W0];
__device__ float g_f2[H1 * W1];
__device__ float g_f3[H2 * W2];
__device__ float g_f4[H3 * W3];

__device__ float g_dn1[NPL * H1 * W1];
__device__ float g_dn2[NPL * H2 * W2];
__device__ float g_dn3[NPL * H3 * W3];
__device__ float g_dn4[NPL * H4 * W4];
__device__ float g_dn5[NPL * H5 * W5];

__device__ float g_F4[NPL * H4 * W4];
__device__ float g_F3[NPL * H3 * W3];
__device__ float g_F2[NPL * H2 * W2];
__device__ float g_F1[NPL * H1 * W1];

// reflect-101 index (jnp.pad mode='reflect'): -1 -> 1, N -> N-2
__device__ __forceinline__ int refl(int i, int n) {
    i = (i < 0) ? -i : i;
    return (i >= n) ? (2 * n - 2 - i) : i;
}

// ---------------------------------------------------------------------------
// f0[j,i] = exp(-(((i-640)^2 + (j-360)^2)) / (2*71^2)); max is 1 so no norm.
// ---------------------------------------------------------------------------
__global__ void genf0_kernel(float* __restrict__ f0) {
    int idx = blockIdx.x * blockDim.x + threadIdx.x;
    if (idx >= F0H * F0W) return;
    int i = idx % F0W;
    int j = idx / F0W;
    float dx = (float)(i - 640);
    float dy = (float)(j - 360);
    f0[idx] = expf(-(dx * dx + dy * dy) / 10082.0f);
}

// ---------------------------------------------------------------------------
// OpenCV-style pyrDown: 5x5 binomial blur (reflect pad 2) then ::2 decimate.
// Generic over plane count / dims. One thread per output pixel.
// ---------------------------------------------------------------------------
__global__ void pyrdown_kernel(const float* __restrict__ src, float* __restrict__ dst,
                               int C, int H, int W, int oH, int oW) {
    int idx = blockIdx.x * blockDim.x + threadIdx.x;
    int total = C * oH * oW;
    if (idx >= total) return;
    int x = idx % oW;
    int y = (idx / oW) % oH;
    int c = idx / (oW * oH);
    const float* s = src + (size_t)c * H * W;

    int ry[5], rx[5];
#pragma unroll
    for (int i = 0; i < 5; i++) {
        ry[i] = refl(2 * y - 2 + i, H);
        rx[i] = refl(2 * x - 2 + i, W);
    }
    const float k0 = 0.0625f, k1 = 0.25f, k2 = 0.375f;
    float acc = 0.0f;
#pragma unroll
    for (int i = 0; i < 5; i++) {
        const float* row = s + (size_t)ry[i] * W;
        float r = k0 * row[rx[0]] + k1 * row[rx[1]] + k2 * row[rx[2]]
                + k1 * row[rx[3]] + k0 * row[rx[4]];
        float kw = (i == 0 || i == 4) ? k0 : ((i == 2) ? k2 : k1);
        acc += kw * r;
    }
    dst[idx] = acc;
}

// ---------------------------------------------------------------------------
// Pointwise pyrUp evaluation: value at (y, x) of blur4(zero_upsample(src)),
// src is (H, W), upsampled grid is (2H, 2W), reflect on the 2H/2W grid.
// Even coordinate: taps at offsets {-2, 0, +2} with weights {1/8, 3/4, 1/8};
// odd: offsets {-1, +1} with weights {1/2, 1/2}. (separable per dim)
// ---------------------------------------------------------------------------
__device__ __forceinline__ float pyrup_at(const float* __restrict__ s,
                                          int H, int W, int y, int x) {
    int sy[3]; float wy[3]; int ny;
    if ((y & 1) == 0) {
        sy[0] = refl(y - 2, 2 * H) >> 1; wy[0] = 0.125f;
        sy[1] = y >> 1;                  wy[1] = 0.75f;
        sy[2] = refl(y + 2, 2 * H) >> 1; wy[2] = 0.125f;
        ny = 3;
    } else {
        sy[0] = (y - 1) >> 1;            wy[0] = 0.5f;
        sy[1] = refl(y + 1, 2 * H) >> 1; wy[1] = 0.5f;
        ny = 2;
    }
    int sx[3]; float wx[3]; int nx;
    if ((x & 1) == 0) {
        sx[0] = refl(x - 2, 2 * W) >> 1; wx[0] = 0.125f;
        sx[1] = x >> 1;                  wx[1] = 0.75f;
        sx[2] = refl(x + 2, 2 * W) >> 1; wx[2] = 0.125f;
        nx = 3;
    } else {
        sx[0] = (x - 1) >> 1;            wx[0] = 0.5f;
        sx[1] = refl(x + 1, 2 * W) >> 1; wx[1] = 0.5f;
        nx = 2;
    }
    float acc = 0.0f;
#pragma unroll 3
    for (int i = 0; i < ny; i++) {
        const float* row = s + (size_t)sy[i] * W;
        float r = 0.0f;
#pragma unroll 3
        for (int j = 0; j < nx; j++) r += wx[j] * row[sx[j]];
        acc += wy[i] * r;
    }
    return acc;
}

// ---------------------------------------------------------------------------
// One reconstruction level (fused):
//   out[p,y,x] = pyrup(Fsrc)[y,x] + (Dcur[p,y,x] - pyrup(Dnext)[y,x]) * w
//   w = filt[y + y1(b), x + x1(b)],  b = p / 3
//   x1 = clamp(trunc(fW/2 - fix_x * invscale), 0, fW - oW)   (dynamic_slice)
// resize_nearest from (2sH, 2sW) down to (oH, oW) is a top-left crop for
// all shapes in this problem, so pyrup is simply evaluated at (y, x).
// For the deepest level Fsrc == Dnext (fovea starts as the last upsample).
// ---------------------------------------------------------------------------
__global__ void recon_kernel(const float* __restrict__ Fsrc,
                             const float* __restrict__ Dnext,
                             int sH, int sW,
                             const float* __restrict__ Dcur,
                             const float* __restrict__ filt, int fH, int fW,
                             const float* __restrict__ fixations,
                             float invscale,
                             float* __restrict__ out, int oH, int oW) {
    int idx = blockIdx.x * blockDim.x + threadIdx.x;
    int total = NPL * oH * oW;
    if (idx >= total) return;
    int x = idx % oW;
    int y = (idx / oW) % oH;
    int p = idx / (oW * oH);
    int b = p / 3;

    float fx = fixations[2 * b]     * invscale;
    float fy = fixations[2 * b + 1] * invscale;
    int x1 = (int)((float)fW * 0.5f - fx);   // trunc toward zero == astype(int32)
    int y1 = (int)((float)fH * 0.5f - fy);
    x1 = min(max(x1, 0), fW - oW);           // lax.dynamic_slice clamp
    y1 = min(max(y1, 0), fH - oH);

    size_t soff = (size_t)p * sH * sW;
    float uF = pyrup_at(Fsrc + soff, sH, sW, y, x);
    float uD = (Fsrc == Dnext) ? uF : pyrup_at(Dnext + soff, sH, sW, y, x);
    float w = filt[(size_t)(y + y1) * fW + (x + x1)];

    out[idx] = uF + (Dcur[idx] - uD) * w;
}

// ---------------------------------------------------------------------------

static inline int nblk(long long n, int t) { return (int)((n + t - 1) / t); }

extern "C" void kernel_launch(void* const* d_in, const int* in_sizes, int n_in,
                              void* d_out, int out_size) {
    (void)in_sizes; (void)n_in; (void)out_size;
    const float* images = (const float*)d_in[0];
    const float* fix    = (const float*)d_in[1];
    float* out = (float*)d_out;

    float *f0, *f1, *f2, *f3, *f4;
    float *dn1, *dn2, *dn3, *dn4, *dn5;
    float *F4, *F3, *F2, *F1;
    cudaGetSymbolAddress((void**)&f0, g_f0);
    cudaGetSymbolAddress((void**)&f1, g_f1);
    cudaGetSymbolAddress((void**)&f2, g_f2);
    cudaGetSymbolAddress((void**)&f3, g_f3);
    cudaGetSymbolAddress((void**)&f4, g_f4);
    cudaGetSymbolAddress((void**)&dn1, g_dn1);
    cudaGetSymbolAddress((void**)&dn2, g_dn2);
    cudaGetSymbolAddress((void**)&dn3, g_dn3);
    cudaGetSymbolAddress((void**)&dn4, g_dn4);
    cudaGetSymbolAddress((void**)&dn5, g_dn5);
    cudaGetSymbolAddress((void**)&F4, g_F4);
    cudaGetSymbolAddress((void**)&F3, g_F3);
    cudaGetSymbolAddress((void**)&F2, g_F2);
    cudaGetSymbolAddress((void**)&F1, g_F1);

    const int T = 256;

    // ---- filters -----------------------------------------------------------
    genf0_kernel<<<nblk((long long)F0H * F0W, T), T>>>(f0);
    pyrdown_kernel<<<nblk((long long)H0 * W0, T), T>>>(f0, f1, 1, F0H, F0W, H0, W0);
    pyrdown_kernel<<<nblk((long long)H1 * W1, T), T>>>(f1, f2, 1, H0, W0, H1, W1);
    pyrdown_kernel<<<nblk((long long)H2 * W2, T), T>>>(f2, f3, 1, H1, W1, H2, W2);
    pyrdown_kernel<<<nblk((long long)H3 * W3, T), T>>>(f3, f4, 1, H2, W2, H3, W3);

    // ---- downsample chain ----------------------------------------------------
    pyrdown_kernel<<<nblk((long long)NPL * H1 * W1, T), T>>>(images, dn1, NPL, H0, W0, H1, W1);
    pyrdown_kernel<<<nblk((long long)NPL * H2 * W2, T), T>>>(dn1, dn2, NPL, H1, W1, H2, W2);
    pyrdown_kernel<<<nblk((long long)NPL * H3 * W3, T), T>>>(dn2, dn3, NPL, H2, W2, H3, W3);
    pyrdown_kernel<<<nblk((long long)NPL * H4 * W4, T), T>>>(dn3, dn4, NPL, H3, W3, H4, W4);
    pyrdown_kernel<<<nblk((long long)NPL * H5 * W5, T), T>>>(dn4, dn5, NPL, H4, W4, H5, W5);

    // ---- reconstruction (levels 4 .. 0) -------------------------------------
    recon_kernel<<<nblk((long long)NPL * H4 * W4, T), T>>>(
        dn5, dn5, H5, W5, dn4, f4, H3, W3, fix, 1.0f / 16.0f, F4, H4, W4);
    recon_kernel<<<nblk((long long)NPL * H3 * W3, T), T>>>(
        F4, dn4, H4, W4, dn3, f3, H2, W2, fix, 1.0f / 8.0f, F3, H3, W3);
    recon_kernel<<<nblk((long long)NPL * H2 * W2, T), T>>>(
        F3, dn3, H3, W3, dn2, f2, H1, W1, fix, 1.0f / 4.0f, F2, H2, W2);
    recon_kernel<<<nblk((long long)NPL * H1 * W1, T), T>>>(
        F2, dn2, H2, W2, dn1, f1, H0, W0, fix, 1.0f / 2.0f, F1, H1, W1);
    recon_kernel<<<nblk((long long)NPL * H0 * W0, T), T>>>(
        F1, dn1, H1, W1, images, f0, F0H, F0W, fix, 1.0f, out, H0, W0);
}

// round 2
// speedup vs baseline: 4.2873x; 4.2873x over previous
#include <cuda_runtime.h>

// ---------------------------------------------------------------------------
// TorchFovea: foveated Laplacian-pyramid blend. (quad-recon + tiled pyrdown)
// ---------------------------------------------------------------------------

#define NPL 96   // 32 batches * 3 channels

#define H0 360
#define W0 640
#define H1 180
#define W1 320
#define H2 90
#define W2 160
#define H3 45
#define W3 80
#define H4 23
#define W4 40
#define H5 12
#define W5 20

#define F0H 719
#define F0W 1279

// ---- scratch ---------------------------------------------------------------
__device__ float g_f0[F0H * F0W];
__device__ float g_f1[H0 * W0];
__device__ float g_f2[H1 * W1];
__device__ float g_f3[H2 * W2];
__device__ float g_f4[H3 * W3];

__device__ float g_dn1[NPL * H1 * W1];
__device__ float g_dn2[NPL * H2 * W2];
__device__ float g_dn3[NPL * H3 * W3];
__device__ float g_dn4[NPL * H4 * W4];
__device__ float g_dn5[NPL * H5 * W5];

__device__ float g_F4[NPL * H4 * W4];
__device__ float g_F3[NPL * H3 * W3];
__device__ float g_F2[NPL * H2 * W2];
__device__ float g_F1[NPL * H1 * W1];

// reflect-101 (jnp.pad mode='reflect')
__device__ __forceinline__ int refl(int i, int n) {
    i = (i < 0) ? -i : i;
    return (i >= n) ? (2 * n - 2 - i) : i;
}

// ---------------------------------------------------------------------------
__global__ void genf0_kernel(float* __restrict__ f0) {
    int idx = blockIdx.x * blockDim.x + threadIdx.x;
    if (idx >= F0H * F0W) return;
    int i = idx % F0W;
    int j = idx / F0W;
    float dx = (float)(i - 640);
    float dy = (float)(j - 360);
    f0[idx] = expf(-(dx * dx + dy * dy) / 10082.0f);
}

// ---------------------------------------------------------------------------
// Tiled separable pyrDown. Block (32,8) computes a 32x8 output tile of one
// plane (blockIdx.z). Stage 1: horizontal 5-tap at decimated columns into
// smem (20 rows x 32 cols). Stage 2: vertical 5-tap from smem.
// ---------------------------------------------------------------------------
#define PDX 32
#define PDY 8
__global__ void pyrdown_tiled(const float* __restrict__ src, float* __restrict__ dst,
                              int H, int W, int oH, int oW) {
    int c = blockIdx.z;
    const float* s = src + (size_t)c * H * W;
    float* d = dst + (size_t)c * oH * oW;
    int ox0 = blockIdx.x * PDX;
    int oy0 = blockIdx.y * PDY;

    __shared__ float hbuf[2 * PDY + 4][PDX];

    const float k0 = 0.0625f, k1 = 0.25f, k2 = 0.375f;
    int tid = threadIdx.y * PDX + threadIdx.x;
    const int NH = (2 * PDY + 4) * PDX;   // 640 entries
#pragma unroll
    for (int idx = tid; idx < NH; idx += PDX * PDY) {
        int j = idx & (PDX - 1);
        int r = idx >> 5;
        int ox = ox0 + j;
        if (ox < oW) {
            int iy = refl(2 * oy0 - 2 + r, H);
            const float* row = s + (size_t)iy * W;
            int ix = 2 * ox;
            float v = k2 * row[ix]
                    + k1 * (row[refl(ix - 1, W)] + row[refl(ix + 1, W)])
                    + k0 * (row[refl(ix - 2, W)] + row[refl(ix + 2, W)]);
            hbuf[r][j] = v;
        }
    }
    __syncthreads();

    int ox = ox0 + threadIdx.x;
    int oy = oy0 + threadIdx.y;
    if (ox < oW && oy < oH) {
        int r = 2 * threadIdx.y;
        float v = k0 * (hbuf[r][threadIdx.x] + hbuf[r + 4][threadIdx.x])
                + k1 * (hbuf[r + 1][threadIdx.x] + hbuf[r + 3][threadIdx.x])
                + k2 * hbuf[r + 2][threadIdx.x];
        d[(size_t)oy * oW + ox] = v;
    }
}

// ---------------------------------------------------------------------------
// Quad reconstruction: each thread computes a 2x2 output block from one 3x3
// source neighborhood of Fsrc and Dnext (separable pyrup weights in regs).
//   out[p,y,x] = pyrup(Fsrc)[y,x] + (Dcur[p,y,x] - pyrup(Dnext)[y,x]) * w
// oW is even for all levels; oH may be odd (odd row guarded).
// ---------------------------------------------------------------------------
__global__ void recon_quad(const float* __restrict__ Fsrc,
                           const float* __restrict__ Dnext,
                           int sH, int sW,
                           const float* __restrict__ Dcur,
                           const float* __restrict__ filt, int fH, int fW,
                           const float* __restrict__ fixations,
                           float invscale,
                           float* __restrict__ out, int oH, int oW) {
    int qW = oW >> 1;
    int qH = (oH + 1) >> 1;
    int qx = blockIdx.x * blockDim.x + threadIdx.x;
    int qy = blockIdx.y * blockDim.y + threadIdx.y;
    if (qx >= qW || qy >= qH) return;
    int p = blockIdx.z;
    int b = p / 3;

    // dynamic_slice offsets (trunc-to-int, then clamp)
    float fx = fixations[2 * b]     * invscale;
    float fy = fixations[2 * b + 1] * invscale;
    int x1 = (int)((float)fW * 0.5f - fx);
    int y1 = (int)((float)fH * 0.5f - fy);
    x1 = min(max(x1, 0), fW - oW);
    y1 = min(max(y1, 0), fH - oH);

    // 3x3 source neighborhood indices (reflect on the 2sH x 2sW grid)
    int xl = (qx == 0) ? 1 : qx - 1;
    int xr = refl(2 * qx + 2, 2 * sW) >> 1;
    int yu = (qy == 0) ? 1 : qy - 1;
    int yd = refl(2 * qy + 2, 2 * sH) >> 1;

    size_t soff = (size_t)p * sH * sW;
    const float* Fs = Fsrc + soff;
    const float* Dn = Dnext + soff;
    bool same = (Fsrc == Dnext);

    float uF_ee, uF_eo, uF_oe, uF_oo;
    float uD_ee, uD_eo, uD_oe, uD_oo;
    {
        const float* r0 = Fs + (size_t)yu * sW;
        const float* r1 = Fs + (size_t)qy * sW;
        const float* r2 = Fs + (size_t)yd * sW;
        float a00 = r0[xl], a01 = r0[qx], a02 = r0[xr];
        float a10 = r1[xl], a11 = r1[qx], a12 = r1[xr];
        float a20 = r2[xl], a21 = r2[qx], a22 = r2[xr];
        float he0 = 0.125f * (a00 + a02) + 0.75f * a01;
        float he1 = 0.125f * (a10 + a12) + 0.75f * a11;
        float he2 = 0.125f * (a20 + a22) + 0.75f * a21;
        float ho0 = 0.5f * (a01 + a02);
        float ho1 = 0.5f * (a11 + a12);
        float ho2 = 0.5f * (a21 + a22);
        uF_ee = 0.125f * (he0 + he2) + 0.75f * he1;
        uF_eo = 0.125f * (ho0 + ho2) + 0.75f * ho1;
        uF_oe = 0.5f * (he1 + he2);
        uF_oo = 0.5f * (ho1 + ho2);
    }
    if (same) {
        uD_ee = uF_ee; uD_eo = uF_eo; uD_oe = uF_oe; uD_oo = uF_oo;
    } else {
        const float* r0 = Dn + (size_t)yu * sW;
        const float* r1 = Dn + (size_t)qy * sW;
        const float* r2 = Dn + (size_t)yd * sW;
        float a00 = r0[xl], a01 = r0[qx], a02 = r0[xr];
        float a10 = r1[xl], a11 = r1[qx], a12 = r1[xr];
        float a20 = r2[xl], a21 = r2[qx], a22 = r2[xr];
        float he0 = 0.125f * (a00 + a02) + 0.75f * a01;
        float he1 = 0.125f * (a10 + a12) + 0.75f * a11;
        float he2 = 0.125f * (a20 + a22) + 0.75f * a21;
        float ho0 = 0.5f * (a01 + a02);
        float ho1 = 0.5f * (a11 + a12);
        float ho2 = 0.5f * (a21 + a22);
        uD_ee = 0.125f * (he0 + he2) + 0.75f * he1;
        uD_eo = 0.125f * (ho0 + ho2) + 0.75f * ho1;
        uD_oe = 0.5f * (he1 + he2);
        uD_oo = 0.5f * (ho1 + ho2);
    }

    int x0 = 2 * qx;
    int y0 = 2 * qy;
    size_t obase = (size_t)p * oH * oW;

    // row y0 (always in range since 2*qy <= oH-1 for qy < qH)
    {
        const float2 dc = *(const float2*)(Dcur + obase + (size_t)y0 * oW + x0);
        const float* fr = filt + (size_t)(y0 + y1) * fW + (x0 + x1);
        float w0 = fr[0], w1 = fr[1];
        float2 o;
        o.x = uF_ee + (dc.x - uD_ee) * w0;
        o.y = uF_eo + (dc.y - uD_eo) * w1;
        *(float2*)(out + obase + (size_t)y0 * oW + x0) = o;
    }
    // row y0+1 (guard for odd oH)
    if (y0 + 1 < oH) {
        const float2 dc = *(const float2*)(Dcur + obase + (size_t)(y0 + 1) * oW + x0);
        const float* fr = filt + (size_t)(y0 + 1 + y1) * fW + (x0 + x1);
        float w0 = fr[0], w1 = fr[1];
        float2 o;
        o.x = uF_oe + (dc.x - uD_oe) * w0;
        o.y = uF_oo + (dc.y - uD_oo) * w1;
        *(float2*)(out + obase + (size_t)(y0 + 1) * oW + x0) = o;
    }
}

// ---------------------------------------------------------------------------

static inline int idiv(int a, int b) { return (a + b - 1) / b; }

static void launch_pyrdown(const float* src, float* dst, int C, int H, int W,
                           int oH, int oW) {
    dim3 blk(PDX, PDY);
    dim3 grd(idiv(oW, PDX), idiv(oH, PDY), C);
    pyrdown_tiled<<<grd, blk>>>(src, dst, H, W, oH, oW);
}

static void launch_recon(const float* Fsrc, const float* Dnext, int sH, int sW,
                         const float* Dcur, const float* filt, int fH, int fW,
                         const float* fix, float invscale,
                         float* out, int oH, int oW) {
    dim3 blk(32, 8);
    dim3 grd(idiv(oW / 2, 32), idiv((oH + 1) / 2, 8), NPL);
    recon_quad<<<grd, blk>>>(Fsrc, Dnext, sH, sW, Dcur, filt, fH, fW,
                             fix, invscale, out, oH, oW);
}

extern "C" void kernel_launch(void* const* d_in, const int* in_sizes, int n_in,
                              void* d_out, int out_size) {
    (void)in_sizes; (void)n_in; (void)out_size;
    const float* images = (const float*)d_in[0];
    const float* fix    = (const float*)d_in[1];
    float* out = (float*)d_out;

    float *f0, *f1, *f2, *f3, *f4;
    float *dn1, *dn2, *dn3, *dn4, *dn5;
    float *F4, *F3, *F2, *F1;
    cudaGetSymbolAddress((void**)&f0, g_f0);
    cudaGetSymbolAddress((void**)&f1, g_f1);
    cudaGetSymbolAddress((void**)&f2, g_f2);
    cudaGetSymbolAddress((void**)&f3, g_f3);
    cudaGetSymbolAddress((void**)&f4, g_f4);
    cudaGetSymbolAddress((void**)&dn1, g_dn1);
    cudaGetSymbolAddress((void**)&dn2, g_dn2);
    cudaGetSymbolAddress((void**)&dn3, g_dn3);
    cudaGetSymbolAddress((void**)&dn4, g_dn4);
    cudaGetSymbolAddress((void**)&dn5, g_dn5);
    cudaGetSymbolAddress((void**)&F4, g_F4);
    cudaGetSymbolAddress((void**)&F3, g_F3);
    cudaGetSymbolAddress((void**)&F2, g_F2);
    cudaGetSymbolAddress((void**)&F1, g_F1);

    // ---- filters ------------------------------------------------------------
    genf0_kernel<<<idiv(F0H * F0W, 256), 256>>>(f0);
    launch_pyrdown(f0, f1, 1, F0H, F0W, H0, W0);
    launch_pyrdown(f1, f2, 1, H0, W0, H1, W1);
    launch_pyrdown(f2, f3, 1, H1, W1, H2, W2);
    launch_pyrdown(f3, f4, 1, H2, W2, H3, W3);

    // ---- downsample chain -----------------------------------------------------
    launch_pyrdown(images, dn1, NPL, H0, W0, H1, W1);
    launch_pyrdown(dn1, dn2, NPL, H1, W1, H2, W2);
    launch_pyrdown(dn2, dn3, NPL, H2, W2, H3, W3);
    launch_pyrdown(dn3, dn4, NPL, H3, W3, H4, W4);
    launch_pyrdown(dn4, dn5, NPL, H4, W4, H5, W5);

    // ---- reconstruction (levels 4 .. 0) --------------------------------------
    launch_recon(dn5, dn5, H5, W5, dn4, f4, H3, W3, fix, 1.0f / 16.0f, F4, H4, W4);
    launch_recon(F4, dn4, H4, W4, dn3, f3, H2, W2, fix, 1.0f / 8.0f, F3, H3, W3);
    launch_recon(F3, dn3, H3, W3, dn2, f2, H1, W1, fix, 1.0f / 4.0f, F2, H2, W2);
    launch_recon(F2, dn2, H2, W2, dn1, f1, H0, W0, fix, 1.0f / 2.0f, F1, H1, W1);
    launch_recon(F1, dn1, H1, W1, images, f0, F0H, F0W, fix, 1.0f, out, H0, W0);
}